// round 6
// baseline (speedup 1.0000x reference)
#include <cuda_runtime.h>
#include <cuda_fp16.h>
#include <cstdint>

#define S_TOK 16384
#define D_DIM 4096
#define N_EXP 64
#define CAP   320
#define KC    64
#define NCHUNK 64
#define BM    128

#define SWZ(o) ((o) ^ (((o) >> 3) & 0x70))

// ---------------- scratch ----------------
__device__ float g_logits[S_TOK * N_EXP];
// W fp16 planes: [chunk][expert][36 words]; rows padded 128B->144B (bank spread)
__device__ __align__(16) uint32_t g_whT[NCHUNK * 2304];
__device__ __align__(16) uint32_t g_wlT[NCHUNK * 2304];   // (w - wh) * 512 in fp16
__device__ int   g_e1[S_TOK];
__device__ int   g_e2[S_TOK];
__device__ int   g_want2[S_TOK];
__device__ float g_g1n[S_TOK];
__device__ float g_g2n[S_TOK];
__device__ int   g_bc1T[64 * 64];    // [expert][block]
__device__ int   g_bc2T[64 * 64];
__device__ int   g_base1T[64 * 64];
__device__ int   g_base2T[64 * 64];
__device__ int   g_cap2[64];
__device__ int   g_nflag;
__device__ int   g_flagged[S_TOK];

// ---------------- PTX helpers ----------------
__device__ __forceinline__ uint32_t smem_to_u32(const void* p) {
    uint32_t a;
    asm("{ .reg .u64 t; cvta.to.shared.u64 t, %1; cvt.u32.u64 %0, t; }" : "=r"(a) : "l"(p));
    return a;
}
#define CP_ASYNC16(dst, src) \
    asm volatile("cp.async.cg.shared.global [%0], [%1], 16;" :: "r"(dst), "l"(src) : "memory")
#define CP_ASYNC_COMMIT()  asm volatile("cp.async.commit_group;" ::: "memory")
#define CP_ASYNC_WAIT0()   asm volatile("cp.async.wait_group 0;" ::: "memory")

#define LDSM_X4(r0, r1, r2, r3, addr) \
    asm volatile("ldmatrix.sync.aligned.m8n8.x4.shared.b16 {%0,%1,%2,%3}, [%4];" \
        : "=r"(r0), "=r"(r1), "=r"(r2), "=r"(r3) : "r"(addr))

#define LDS32(r, addr) \
    asm volatile("ld.shared.b32 %0, [%1];" : "=r"(r) : "r"(addr))

#define MMA_FP16(d, a, b0, b1) \
    asm volatile("mma.sync.aligned.m16n8k16.row.col.f32.f16.f16.f32 " \
        "{%0,%1,%2,%3}, {%4,%5,%6,%7}, {%8,%9}, {%0,%1,%2,%3};" \
        : "+f"((d)[0]), "+f"((d)[1]), "+f"((d)[2]), "+f"((d)[3]) \
        : "r"((a)[0]), "r"((a)[1]), "r"((a)[2]), "r"((a)[3]), "r"(b0), "r"(b1))

// gemm smem layout
#define XS(s)  (sb + (s) * 16384)
#define WHS(s) (sb + 32768 + (s) * 18432)
#define WLS(s) (sb + 32768 + (s) * 18432 + 9216)
#define GEMM_SMEM 69632

// ---------------- W pre-conversion (also resets flag counter) ----------------
__global__ __launch_bounds__(256)
void wconv_kernel(const float* __restrict__ W) {
    const int pid = blockIdx.x * 256 + threadIdx.x;   // 0..131071
    if (pid == 0) g_nflag = 0;
    const int n = pid >> 11;                          // expert 0..63
    const int j = pid & 2047;                         // k-pair 0..2047
    const float2 v = *(const float2*)(W + (size_t)n * D_DIM + j * 2);
    const __half h0 = __float2half_rn(v.x);
    const __half h1 = __float2half_rn(v.y);
    const __half l0 = __float2half_rn((v.x - __half2float(h0)) * 512.0f);
    const __half l1 = __float2half_rn((v.y - __half2float(h1)) * 512.0f);
    const uint32_t hp = (uint32_t)__half_as_ushort(h0) | ((uint32_t)__half_as_ushort(h1) << 16);
    const uint32_t lp = (uint32_t)__half_as_ushort(l0) | ((uint32_t)__half_as_ushort(l1) << 16);
    const int idx = (j >> 5) * 2304 + n * 36 + (j & 31);
    g_whT[idx] = hp;
    g_wlT[idx] = lp;
}

// ---------------- HMMA GEMM: fp16 2-product, dual accumulators ----------------
__global__ __launch_bounds__(512, 1)
void gemm_mma(const float* __restrict__ X) {
    extern __shared__ __align__(1024) char smem[];
    const uint32_t sb = smem_to_u32(smem);
    const int tid = threadIdx.x, wid = tid >> 5, lane = tid & 31;
    const int m0 = blockIdx.x * BM;
    const int warp_m = wid & 3, warp_n = wid >> 2;   // 4M x 4N, warp tile m32 x n16

    float acc_h[2][2][4], acc_l[2][2][4];
#pragma unroll
    for (int a = 0; a < 2; ++a)
#pragma unroll
        for (int b = 0; b < 2; ++b)
#pragma unroll
            for (int q = 0; q < 4; ++q) { acc_h[a][b][q] = 0.f; acc_l[a][b][q] = 0.f; }

    const int xrow = tid >> 2, xc4 = tid & 3;
    const float4* xp = (const float4*)(X + (size_t)(m0 + xrow) * D_DIM);

    const uint32_t a_b0  = (uint32_t)((warp_m * 32 + (lane & 15)) * 128 + (lane >> 4) * 16);
    const uint32_t b_off = (uint32_t)((warp_n * 16 + (lane >> 2)) * 144 + (lane & 3) * 4);

    auto loadB = [&](int c, int s) {
        const char* gh = (const char*)(g_whT + c * 2304);
        const char* gl = (const char*)(g_wlT + c * 2304);
        const uint32_t wh = WHS(s), wl = WLS(s);
#pragma unroll
        for (int i2 = 0; i2 < 3; ++i2) {
            const int idx = tid + i2 * 512;
            if (idx < 576)       CP_ASYNC16(wh + idx * 16, gh + idx * 16);
            else if (idx < 1152) CP_ASYNC16(wl + (idx - 576) * 16, gl + (idx - 576) * 16);
        }
    };
    auto loadx = [&](int c, float4* v) {
#pragma unroll
        for (int it = 0; it < 4; ++it)
            v[it] = xp[c * 16 + xc4 + it * 4];
    };
    auto storeXS = [&](int s, const float4* v) {
        const uint32_t xs = XS(s);
#pragma unroll
        for (int it = 0; it < 4; ++it) {
            const __half2 h01 = __floats2half2_rn(v[it].x, v[it].y);
            const __half2 h23 = __floats2half2_rn(v[it].z, v[it].w);
            const uint32_t p0 = *(const uint32_t*)&h01;
            const uint32_t p1 = *(const uint32_t*)&h23;
            const uint32_t off = SWZ((uint32_t)(xrow * 128 + (xc4 + it * 4) * 8));
            asm volatile("st.shared.v2.b32 [%0], {%1,%2};" :: "r"(xs + off), "r"(p0), "r"(p1) : "memory");
        }
    };

    // prologue: chunk 0
    float4 v[4];
    loadB(0, 0);
    CP_ASYNC_COMMIT();
    loadx(0, v);
    storeXS(0, v);
    CP_ASYNC_WAIT0();
    __syncthreads();

    for (int c = 0; c < NCHUNK; ++c) {
        const int s = c & 1;
        float4 nv[4];
        if (c + 1 < NCHUNK) {
            loadB(c + 1, s ^ 1);
            CP_ASYNC_COMMIT();
            loadx(c + 1, nv);
        }
        const uint32_t xs = XS(s), wh = WHS(s), wl = WLS(s);
#pragma unroll
        for (int ks = 0; ks < 4; ++ks) {
            uint32_t ah[2][4];
            LDSM_X4(ah[0][0], ah[0][1], ah[0][2], ah[0][3], xs + SWZ(a_b0 + ks * 32));
            LDSM_X4(ah[1][0], ah[1][1], ah[1][2], ah[1][3], xs + SWZ(a_b0 + 2048 + ks * 32));
            uint32_t bh[2][2], bl[2][2];
#pragma unroll
            for (int nt = 0; nt < 2; ++nt) {
                const uint32_t bo = b_off + nt * 1152 + ks * 32;
                LDS32(bh[nt][0], wh + bo);
                LDS32(bh[nt][1], wh + bo + 16);
                LDS32(bl[nt][0], wl + bo);
                LDS32(bl[nt][1], wl + bo + 16);
            }
#pragma unroll
            for (int mt = 0; mt < 2; ++mt)
#pragma unroll
                for (int nt = 0; nt < 2; ++nt)
                    MMA_FP16(acc_h[mt][nt], ah[mt], bh[nt][0], bh[nt][1]);
#pragma unroll
            for (int mt = 0; mt < 2; ++mt)
#pragma unroll
                for (int nt = 0; nt < 2; ++nt)
                    MMA_FP16(acc_l[mt][nt], ah[mt], bl[nt][0], bl[nt][1]);
        }
        if (c + 1 < NCHUNK) storeXS(s ^ 1, nv);
        CP_ASYNC_WAIT0();
        __syncthreads();
    }

    // epilogue: logits = acc_h + acc_l/512
    const int r0 = m0 + warp_m * 32 + (lane >> 2);
    const int c0 = warp_n * 16 + (lane & 3) * 2;
    const float inv = 1.0f / 512.0f;
#pragma unroll
    for (int mt = 0; mt < 2; ++mt)
#pragma unroll
        for (int nt = 0; nt < 2; ++nt) {
            const float f0 = acc_h[mt][nt][0] + acc_l[mt][nt][0] * inv;
            const float f1 = acc_h[mt][nt][1] + acc_l[mt][nt][1] * inv;
            const float f2 = acc_h[mt][nt][2] + acc_l[mt][nt][2] * inv;
            const float f3 = acc_h[mt][nt][3] + acc_l[mt][nt][3] * inv;
            const int r = r0 + mt * 16, cc = c0 + nt * 8;
            *(float2*)&g_logits[(size_t)r * 64 + cc]       = make_float2(f0, f1);
            *(float2*)&g_logits[(size_t)(r + 8) * 64 + cc] = make_float2(f2, f3);
        }
}

// ---------------- Threefry-2x32 (JAX partitionable, key(1)) ----------------
__device__ __forceinline__ void threefry2x32(uint32_t x0, uint32_t x1,
                                             uint32_t& o0, uint32_t& o1) {
    const uint32_t k0 = 0u, k1 = 1u, k2 = 0x1BD11BDBu;
    x0 += k0; x1 += k1;
#define TFR(r) { x0 += x1; x1 = (x1 << (r)) | (x1 >> (32 - (r))); x1 ^= x0; }
    TFR(13) TFR(15) TFR(26) TFR(6)  x0 += k1; x1 += k2 + 1u;
    TFR(17) TFR(29) TFR(16) TFR(24) x0 += k2; x1 += k0 + 2u;
    TFR(13) TFR(15) TFR(26) TFR(6)  x0 += k0; x1 += k1 + 3u;
    TFR(17) TFR(29) TFR(16) TFR(24) x0 += k1; x1 += k2 + 4u;
    TFR(13) TFR(15) TFR(26) TFR(6)  x0 += k2; x1 += k0 + 5u;
#undef TFR
    o0 = x0; o1 = x1;
}
__device__ __forceinline__ float jax_uniform_partitionable(uint32_t i) {
    uint32_t o0, o1;
    threefry2x32(0u, i, o0, o1);
    const uint32_t bits = o0 ^ o1;
    return __uint_as_float((bits >> 9) | 0x3f800000u) - 1.0f;
}

// ---------------- fused topk + softmax + want2 + flags + block histogram ----------------
__global__ __launch_bounds__(256)
void topk256() {
    __shared__ int c1[64], c2[64];
    const int t = threadIdx.x, blk = blockIdx.x;
    const int i = blk * 256 + t;
    if (t < 64) { c1[t] = 0; c2[t] = 0; }
    __syncthreads();

    float4 L[16];
    const float4* lp = (const float4*)(g_logits + (size_t)i * 64);
#pragma unroll
    for (int q = 0; q < 16; ++q) L[q] = lp[q];

    float v1 = -3.4e38f, v2 = -3.4e38f, v3 = -3.4e38f;
    int i1 = 0, i2 = 0;
#pragma unroll
    for (int q = 0; q < 16; ++q) {
        const float e[4] = {L[q].x, L[q].y, L[q].z, L[q].w};
#pragma unroll
        for (int r = 0; r < 4; ++r) {
            const float x = e[r]; const int idx = q * 4 + r;
            if (x > v1)      { v3 = v2; v2 = v1; i2 = i1; v1 = x; i1 = idx; }
            else if (x > v2) { v3 = v2; v2 = x; i2 = idx; }
            else if (x > v3) { v3 = x; }
        }
    }
    float s = 0.f;
#pragma unroll
    for (int q = 0; q < 16; ++q)
        s += expf(L[q].x - v1) + expf(L[q].y - v1) + expf(L[q].z - v1) + expf(L[q].w - v1);

    const float g1 = 1.0f / s;
    const float g2 = expf(v2 - v1) / s;
    const float denom = g1 + g2;
    const float g1n = g1 / denom, g2n = g2 / denom;
    const float rnd = jax_uniform_partitionable((uint32_t)i);
    const int want2 = (rnd < 2.0f * g2n) ? 1 : 0;

    g_e1[i] = i1; g_e2[i] = i2;
    g_g1n[i] = g1n; g_g2n[i] = g2n;
    g_want2[i] = want2;

    const float TAU = 1e-3f;
    if ((v1 - v2) < TAU || (v2 - v3) < TAU || fabsf(rnd - 2.0f * g2n) < TAU) {
        const int k = atomicAdd(&g_nflag, 1);
        g_flagged[k] = i;
    }
    atomicAdd(&c1[i1], 1);
    if (want2) atomicAdd(&c2[i2], 1);
    __syncthreads();
    if (t < 64) { g_bc1T[t * 64 + blk] = c1[t]; g_bc2T[t * 64 + blk] = c2[t]; }
}

// ---------------- exact fp32 rescue (+ histogram patching) ----------------
__global__ __launch_bounds__(256)
void rescue_kernel(const float* __restrict__ X, const float* __restrict__ W) {
    __shared__ float part[64][4];
    __shared__ float lg[64];
    const int t = threadIdx.x, e = t >> 2, p = t & 3;
    const int nf = g_nflag;

    for (int fi = blockIdx.x; fi < nf; fi += gridDim.x) {
        const int i = g_flagged[fi];
        const float4* xr = (const float4*)(X + (size_t)i * D_DIM + p * 1024);
        const float4* wr = (const float4*)(W + (size_t)e * D_DIM + p * 1024);
        float a0 = 0.f, a1 = 0.f, a2 = 0.f, a3 = 0.f;
        for (int j = 0; j < 256; ++j) {
            const float4 xa = xr[j];
            const float4 wa = wr[j];
            a0 = fmaf(xa.x, wa.x, a0);
            a1 = fmaf(xa.y, wa.y, a1);
            a2 = fmaf(xa.z, wa.z, a2);
            a3 = fmaf(xa.w, wa.w, a3);
        }
        part[e][p] = ((a0 + a1) + a2) + a3;
        __syncthreads();
        if (t < 64)
            lg[t] = ((part[t][0] + part[t][1]) + part[t][2]) + part[t][3];
        __syncthreads();

        if (t < 32) {
            const int lane = t;
            const float l0 = lg[lane];
            const float l1 = lg[lane + 32];
            const float NEG_INF = __int_as_float(0xff800000);

            float v; int idx;
            if (l1 > l0) { v = l1; idx = lane + 32; } else { v = l0; idx = lane; }
#pragma unroll
            for (int off = 16; off; off >>= 1) {
                float ov = __shfl_xor_sync(0xffffffffu, v, off);
                int   oi = __shfl_xor_sync(0xffffffffu, idx, off);
                if (ov > v || (ov == v && oi < idx)) { v = ov; idx = oi; }
            }
            const float mm = v; const int i1 = idx;

            float w0 = (lane == i1) ? NEG_INF : l0;
            float w1 = (lane + 32 == i1) ? NEG_INF : l1;
            float v2; int idx2;
            if (w1 > w0) { v2 = w1; idx2 = lane + 32; } else { v2 = w0; idx2 = lane; }
#pragma unroll
            for (int off = 16; off; off >>= 1) {
                float ov = __shfl_xor_sync(0xffffffffu, v2, off);
                int   oi = __shfl_xor_sync(0xffffffffu, idx2, off);
                if (ov > v2 || (ov == v2 && oi < idx2)) { v2 = ov; idx2 = oi; }
            }

            float s = expf(l0 - mm) + expf(l1 - mm);
#pragma unroll
            for (int off = 16; off; off >>= 1)
                s += __shfl_xor_sync(0xffffffffu, s, off);

            if (lane == 0) {
                const float g1 = 1.0f / s;
                const float g2 = expf(v2 - mm) / s;
                const float denom = g1 + g2;
                const float g2n = g2 / denom;
                const float rnd = jax_uniform_partitionable((uint32_t)i);
                const int w2 = (rnd < 2.0f * g2n) ? 1 : 0;

                const int blkb = i >> 8;
                const int oe1 = g_e1[i], oe2 = g_e2[i], ow2 = g_want2[i];
                if (i1 != oe1) {
                    atomicSub(&g_bc1T[oe1 * 64 + blkb], 1);
                    atomicAdd(&g_bc1T[i1 * 64 + blkb], 1);
                }
                if (ow2) atomicSub(&g_bc2T[oe2 * 64 + blkb], 1);
                if (w2)  atomicAdd(&g_bc2T[idx2 * 64 + blkb], 1);

                g_e1[i] = i1;
                g_e2[i] = idx2;
                g_g1n[i] = g1 / denom;
                g_g2n[i] = g2n;
                g_want2[i] = w2;
            }
        }
        __syncthreads();
    }
}

// ---------------- cross-block scan (transposed, int4) ----------------
__global__ void scan_kernel() {
    const int e = threadIdx.x;
    if (e >= 64) return;
    int4 buf[16];
    const int4* s1 = (const int4*)(g_bc1T + e * 64);
#pragma unroll
    for (int q = 0; q < 16; ++q) buf[q] = s1[q];
    int r1 = 0;
#pragma unroll
    for (int q = 0; q < 16; ++q) {
        g_base1T[e * 64 + q * 4 + 0] = r1; r1 += buf[q].x;
        g_base1T[e * 64 + q * 4 + 1] = r1; r1 += buf[q].y;
        g_base1T[e * 64 + q * 4 + 2] = r1; r1 += buf[q].z;
        g_base1T[e * 64 + q * 4 + 3] = r1; r1 += buf[q].w;
    }
    const int4* s2 = (const int4*)(g_bc2T + e * 64);
#pragma unroll
    for (int q = 0; q < 16; ++q) buf[q] = s2[q];
    int r2 = 0;
#pragma unroll
    for (int q = 0; q < 16; ++q) {
        g_base2T[e * 64 + q * 4 + 0] = r2; r2 += buf[q].x;
        g_base2T[e * 64 + q * 4 + 1] = r2; r2 += buf[q].y;
        g_base2T[e * 64 + q * 4 + 2] = r2; r2 += buf[q].z;
        g_base2T[e * 64 + q * 4 + 3] = r2; r2 += buf[q].w;
    }
    g_cap2[e] = CAP - (r1 < CAP ? r1 : CAP);
}

// ---------------- final ranks + full-row write (zeroing fused) ----------------
__global__ __launch_bounds__(256)
void assign_kernel(float* __restrict__ out) {
    __shared__ int wc1[8][64];
    __shared__ int wc2[8][64];
    const int t = threadIdx.x, warp = t >> 5, lane = t & 31;
    const int blk = blockIdx.x;

    ((int*)wc1)[t] = 0; ((int*)wc1)[t + 256] = 0;
    ((int*)wc2)[t] = 0; ((int*)wc2)[t + 256] = 0;
    __syncthreads();

    const int i  = blk * 256 + t;
    const int e1 = g_e1[i], e2 = g_e2[i], want2 = g_want2[i];
    const unsigned lt = (1u << lane) - 1u;

    const unsigned m1 = __match_any_sync(0xffffffffu, e1);
    const int lr1 = __popc(m1 & lt);
    if (lr1 == 0) wc1[warp][e1] = __popc(m1);

    const unsigned act2 = __ballot_sync(0xffffffffu, want2);
    const unsigned m2 = __match_any_sync(0xffffffffu, e2) & act2;
    const int lr2 = __popc(m2 & lt);
    if (want2 && lr2 == 0) wc2[warp][e2] = __popc(m2);
    __syncthreads();

    int off1 = 0, off2 = 0;
    for (int w = 0; w < warp; ++w) {
        off1 += wc1[w][e1];
        off2 += wc2[w][e2];
    }

    const int pos1 = g_base1T[e1 * 64 + blk] + off1 + lr1 + 1;
    const int pos2 = g_base2T[e2 * 64 + blk] + off2 + lr2 + 1;
    const float val1 = (pos1 <= CAP) ? g_g1n[i] : 0.f;
    const float val2 = (want2 && pos2 <= g_cap2[e2]) ? g_g2n[i] : 0.f;

    float4* op = (float4*)(out + (size_t)i * 64);
#pragma unroll
    for (int q = 0; q < 16; ++q) {
        float4 z = make_float4(0.f, 0.f, 0.f, 0.f);
        if ((e1 >> 2) == q) ((float*)&z)[e1 & 3] = val1;
        if ((e2 >> 2) == q) ((float*)&z)[e2 & 3] = val2;
        op[q] = z;
    }
}

// ---------------- launcher ----------------
extern "C" void kernel_launch(void* const* d_in, const int* in_sizes, int n_in,
                              void* d_out, int out_size) {
    const float* x = (const float*)d_in[0];
    const float* w = (const float*)d_in[1];
    float* out = (float*)d_out;

    cudaFuncSetAttribute(gemm_mma, cudaFuncAttributeMaxDynamicSharedMemorySize, GEMM_SMEM);

    wconv_kernel<<<512, 256>>>(w);
    gemm_mma<<<S_TOK / BM, 512, GEMM_SMEM>>>(x);
    topk256<<<S_TOK / 256, 256>>>();
    rescue_kernel<<<148, 256>>>(x, w);
    scan_kernel<<<1, 64>>>();
    assign_kernel<<<S_TOK / 256, 256>>>(out);
}

// round 7
// speedup vs baseline: 1.3185x; 1.3185x over previous
#include <cuda_runtime.h>
#include <cuda_fp16.h>
#include <cstdint>

#define S_TOK 16384
#define D_DIM 4096
#define N_EXP 64
#define CAP   320
#define KC    64
#define NCHUNK 64
#define BM    128

#define SWZ(o) ((o) ^ (((o) >> 3) & 0x70))

// ---------------- scratch ----------------
__device__ float g_logits[S_TOK * N_EXP];
// W fp16 plane: [chunk][expert][36 words]; rows padded 128B->144B (bank spread)
__device__ __align__(16) uint32_t g_whT[NCHUNK * 2304];
__device__ int   g_e1[S_TOK];
__device__ int   g_e2[S_TOK];
__device__ int   g_want2[S_TOK];
__device__ float g_g1n[S_TOK];
__device__ float g_g2n[S_TOK];
__device__ int   g_bc1T[64 * 64];    // [expert][block]
__device__ int   g_bc2T[64 * 64];
__device__ int   g_base1T[64 * 64];
__device__ int   g_base2T[64 * 64];
__device__ int   g_cap2[64];
__device__ int   g_nflag;
__device__ int   g_flagged[S_TOK];

// ---------------- PTX helpers ----------------
__device__ __forceinline__ uint32_t smem_to_u32(const void* p) {
    uint32_t a;
    asm("{ .reg .u64 t; cvta.to.shared.u64 t, %1; cvt.u32.u64 %0, t; }" : "=r"(a) : "l"(p));
    return a;
}
#define CP_ASYNC16(dst, src) \
    asm volatile("cp.async.cg.shared.global [%0], [%1], 16;" :: "r"(dst), "l"(src) : "memory")
#define CP_ASYNC_COMMIT()  asm volatile("cp.async.commit_group;" ::: "memory")
#define CP_ASYNC_WAIT0()   asm volatile("cp.async.wait_group 0;" ::: "memory")

#define LDSM_X4(r0, r1, r2, r3, addr) \
    asm volatile("ldmatrix.sync.aligned.m8n8.x4.shared.b16 {%0,%1,%2,%3}, [%4];" \
        : "=r"(r0), "=r"(r1), "=r"(r2), "=r"(r3) : "r"(addr))

#define LDS32(r, addr) \
    asm volatile("ld.shared.b32 %0, [%1];" : "=r"(r) : "r"(addr))

#define MMA_FP16(d, a, b0, b1) \
    asm volatile("mma.sync.aligned.m16n8k16.row.col.f32.f16.f16.f32 " \
        "{%0,%1,%2,%3}, {%4,%5,%6,%7}, {%8,%9}, {%0,%1,%2,%3};" \
        : "+f"((d)[0]), "+f"((d)[1]), "+f"((d)[2]), "+f"((d)[3]) \
        : "r"((a)[0]), "r"((a)[1]), "r"((a)[2]), "r"((a)[3]), "r"(b0), "r"(b1))

// gemm smem layout
#define XS(s)  (sb + (s) * 16384)
#define WHS(s) (sb + 32768 + (s) * 9216)
#define GEMM_SMEM 51200

// ---------------- W pre-conversion (also resets flag counter) ----------------
__global__ __launch_bounds__(256)
void wconv_kernel(const float* __restrict__ W) {
    const int pid = blockIdx.x * 256 + threadIdx.x;   // 0..131071
    if (pid == 0) g_nflag = 0;
    const int n = pid >> 11;                          // expert 0..63
    const int j = pid & 2047;                         // k-pair 0..2047
    const float2 v = *(const float2*)(W + (size_t)n * D_DIM + j * 2);
    const __half h0 = __float2half_rn(v.x);
    const __half h1 = __float2half_rn(v.y);
    const uint32_t hp = (uint32_t)__half_as_ushort(h0) | ((uint32_t)__half_as_ushort(h1) << 16);
    g_whT[(j >> 5) * 2304 + n * 36 + (j & 31)] = hp;
}

// ---------------- HMMA GEMM: single fp16 product ----------------
__global__ __launch_bounds__(512, 1)
void gemm_mma(const float* __restrict__ X) {
    extern __shared__ __align__(1024) char smem[];
    const uint32_t sb = smem_to_u32(smem);
    const int tid = threadIdx.x, wid = tid >> 5, lane = tid & 31;
    const int m0 = blockIdx.x * BM;
    const int warp_m = wid & 3, warp_n = wid >> 2;   // 4M x 4N, warp tile m32 x n16

    float acc[2][2][4];
#pragma unroll
    for (int a = 0; a < 2; ++a)
#pragma unroll
        for (int b = 0; b < 2; ++b)
#pragma unroll
            for (int q = 0; q < 4; ++q) acc[a][b][q] = 0.f;

    const int xrow = tid >> 2, xc4 = tid & 3;
    const float4* xp = (const float4*)(X + (size_t)(m0 + xrow) * D_DIM);

    const uint32_t a_b0  = (uint32_t)((warp_m * 32 + (lane & 15)) * 128 + (lane >> 4) * 16);
    const uint32_t b_off = (uint32_t)((warp_n * 16 + (lane >> 2)) * 144 + (lane & 3) * 4);

    auto loadB = [&](int c, int s) {
        const char* gh = (const char*)(g_whT + c * 2304);
        const uint32_t wh = WHS(s);
        CP_ASYNC16(wh + tid * 16, gh + tid * 16);
        if (tid < 64) CP_ASYNC16(wh + (512 + tid) * 16, gh + (512 + tid) * 16);
    };
    auto loadx = [&](int c, float4* v) {
#pragma unroll
        for (int it = 0; it < 4; ++it)
            v[it] = xp[c * 16 + xc4 + it * 4];
    };
    auto storeXS = [&](int s, const float4* v) {
        const uint32_t xs = XS(s);
#pragma unroll
        for (int it = 0; it < 4; ++it) {
            const __half2 h01 = __floats2half2_rn(v[it].x, v[it].y);
            const __half2 h23 = __floats2half2_rn(v[it].z, v[it].w);
            const uint32_t p0 = *(const uint32_t*)&h01;
            const uint32_t p1 = *(const uint32_t*)&h23;
            const uint32_t off = SWZ((uint32_t)(xrow * 128 + (xc4 + it * 4) * 8));
            asm volatile("st.shared.v2.b32 [%0], {%1,%2};" :: "r"(xs + off), "r"(p0), "r"(p1) : "memory");
        }
    };

    // prologue
    float4 v[4];
    loadB(0, 0);
    CP_ASYNC_COMMIT();
    loadx(0, v);
    storeXS(0, v);
    CP_ASYNC_WAIT0();
    __syncthreads();

    for (int c = 0; c < NCHUNK; ++c) {
        const int s = c & 1;
        float4 nv[4];
        if (c + 1 < NCHUNK) {
            loadB(c + 1, s ^ 1);
            CP_ASYNC_COMMIT();
            loadx(c + 1, nv);
        }
        const uint32_t xs = XS(s), wh = WHS(s);
#pragma unroll
        for (int ks = 0; ks < 4; ++ks) {
            uint32_t ah[2][4];
            LDSM_X4(ah[0][0], ah[0][1], ah[0][2], ah[0][3], xs + SWZ(a_b0 + ks * 32));
            LDSM_X4(ah[1][0], ah[1][1], ah[1][2], ah[1][3], xs + SWZ(a_b0 + 2048 + ks * 32));
            uint32_t bh[2][2];
#pragma unroll
            for (int nt = 0; nt < 2; ++nt) {
                const uint32_t bo = b_off + nt * 1152 + ks * 32;
                LDS32(bh[nt][0], wh + bo);
                LDS32(bh[nt][1], wh + bo + 16);
            }
#pragma unroll
            for (int mt = 0; mt < 2; ++mt)
#pragma unroll
                for (int nt = 0; nt < 2; ++nt)
                    MMA_FP16(acc[mt][nt], ah[mt], bh[nt][0], bh[nt][1]);
        }
        if (c + 1 < NCHUNK) storeXS(s ^ 1, nv);
        CP_ASYNC_WAIT0();
        __syncthreads();
    }

    const int r0 = m0 + warp_m * 32 + (lane >> 2);
    const int c0 = warp_n * 16 + (lane & 3) * 2;
#pragma unroll
    for (int mt = 0; mt < 2; ++mt)
#pragma unroll
        for (int nt = 0; nt < 2; ++nt) {
            const int r = r0 + mt * 16, cc = c0 + nt * 8;
            *(float2*)&g_logits[(size_t)r * 64 + cc]       = make_float2(acc[mt][nt][0], acc[mt][nt][1]);
            *(float2*)&g_logits[(size_t)(r + 8) * 64 + cc] = make_float2(acc[mt][nt][2], acc[mt][nt][3]);
        }
}

// ---------------- Threefry-2x32 (JAX partitionable, key(1)) ----------------
__device__ __forceinline__ void threefry2x32(uint32_t x0, uint32_t x1,
                                             uint32_t& o0, uint32_t& o1) {
    const uint32_t k0 = 0u, k1 = 1u, k2 = 0x1BD11BDBu;
    x0 += k0; x1 += k1;
#define TFR(r) { x0 += x1; x1 = (x1 << (r)) | (x1 >> (32 - (r))); x1 ^= x0; }
    TFR(13) TFR(15) TFR(26) TFR(6)  x0 += k1; x1 += k2 + 1u;
    TFR(17) TFR(29) TFR(16) TFR(24) x0 += k2; x1 += k0 + 2u;
    TFR(13) TFR(15) TFR(26) TFR(6)  x0 += k0; x1 += k1 + 3u;
    TFR(17) TFR(29) TFR(16) TFR(24) x0 += k1; x1 += k2 + 4u;
    TFR(13) TFR(15) TFR(26) TFR(6)  x0 += k2; x1 += k0 + 5u;
#undef TFR
    o0 = x0; o1 = x1;
}
__device__ __forceinline__ float jax_uniform_partitionable(uint32_t i) {
    uint32_t o0, o1;
    threefry2x32(0u, i, o0, o1);
    const uint32_t bits = o0 ^ o1;
    return __uint_as_float((bits >> 9) | 0x3f800000u) - 1.0f;
}

// ---------------- fused topk + softmax + want2 + flags + block histogram ----------------
__global__ __launch_bounds__(256)
void topk256() {
    __shared__ int c1[64], c2[64];
    const int t = threadIdx.x, blk = blockIdx.x;
    const int i = blk * 256 + t;
    if (t < 64) { c1[t] = 0; c2[t] = 0; }
    __syncthreads();

    float4 L[16];
    const float4* lp = (const float4*)(g_logits + (size_t)i * 64);
#pragma unroll
    for (int q = 0; q < 16; ++q) L[q] = lp[q];

    float v1 = -3.4e38f, v2 = -3.4e38f, v3 = -3.4e38f;
    int i1 = 0, i2 = 0;
#pragma unroll
    for (int q = 0; q < 16; ++q) {
        const float e[4] = {L[q].x, L[q].y, L[q].z, L[q].w};
#pragma unroll
        for (int r = 0; r < 4; ++r) {
            const float x = e[r]; const int idx = q * 4 + r;
            if (x > v1)      { v3 = v2; v2 = v1; i2 = i1; v1 = x; i1 = idx; }
            else if (x > v2) { v3 = v2; v2 = x; i2 = idx; }
            else if (x > v3) { v3 = x; }
        }
    }
    float s = 0.f;
#pragma unroll
    for (int q = 0; q < 16; ++q)
        s += expf(L[q].x - v1) + expf(L[q].y - v1) + expf(L[q].z - v1) + expf(L[q].w - v1);

    const float g1 = 1.0f / s;
    const float g2 = expf(v2 - v1) / s;
    const float denom = g1 + g2;
    const float g1n = g1 / denom, g2n = g2 / denom;
    const float rnd = jax_uniform_partitionable((uint32_t)i);
    const int want2 = (rnd < 2.0f * g2n) ? 1 : 0;

    g_e1[i] = i1; g_e2[i] = i2;
    g_g1n[i] = g1n; g_g2n[i] = g2n;
    g_want2[i] = want2;

    const float TAU_GAP = 2e-3f, TAU_RND = 1.2e-3f;
    if ((v1 - v2) < TAU_GAP || (v2 - v3) < TAU_GAP || fabsf(rnd - 2.0f * g2n) < TAU_RND) {
        const int k = atomicAdd(&g_nflag, 1);
        g_flagged[k] = i;
    }
    atomicAdd(&c1[i1], 1);
    if (want2) atomicAdd(&c2[i2], 1);
    __syncthreads();
    if (t < 64) { g_bc1T[t * 64 + blk] = c1[t]; g_bc2T[t * 64 + blk] = c2[t]; }
}

// ---------------- exact fp32 rescue, coalesced (+ histogram patching) ----------------
__global__ __launch_bounds__(256)
void rescue_kernel(const float* __restrict__ X, const float* __restrict__ W) {
    __shared__ __align__(16) float xs[D_DIM];
    __shared__ float lg[64];
    const int t = threadIdx.x, warp = t >> 5, lane = t & 31;
    const int nf = g_nflag;

    for (int fi = blockIdx.x; fi < nf; fi += gridDim.x) {
        const int i = g_flagged[fi];

        // stage x row coalesced
        {
            const float4* xr = (const float4*)(X + (size_t)i * D_DIM);
            float4* xd = (float4*)xs;
#pragma unroll
            for (int q = 0; q < 4; ++q) xd[t + q * 256] = xr[t + q * 256];
        }
        __syncthreads();

        // 8 passes x 8 warps: warp computes expert e = pass*8 + warp (coalesced W reads)
#pragma unroll
        for (int pass = 0; pass < 8; ++pass) {
            const int e = pass * 8 + warp;
            const float4* wr = (const float4*)(W + (size_t)e * D_DIM);
            const float4* xv = (const float4*)xs;
            float a0 = 0.f, a1 = 0.f, a2 = 0.f, a3 = 0.f;
#pragma unroll 8
            for (int j = 0; j < 32; ++j) {
                const float4 wa = wr[j * 32 + lane];
                const float4 xa = xv[j * 32 + lane];
                a0 = fmaf(xa.x, wa.x, a0);
                a1 = fmaf(xa.y, wa.y, a1);
                a2 = fmaf(xa.z, wa.z, a2);
                a3 = fmaf(xa.w, wa.w, a3);
            }
            float tot = ((a0 + a1) + a2) + a3;
#pragma unroll
            for (int off = 16; off; off >>= 1)
                tot += __shfl_xor_sync(0xffffffffu, tot, off);
            if (lane == 0) lg[e] = tot;
        }
        __syncthreads();

        if (t < 32) {
            const float l0 = lg[lane];
            const float l1 = lg[lane + 32];
            const float NEG_INF = __int_as_float(0xff800000);

            float v; int idx;
            if (l1 > l0) { v = l1; idx = lane + 32; } else { v = l0; idx = lane; }
#pragma unroll
            for (int off = 16; off; off >>= 1) {
                float ov = __shfl_xor_sync(0xffffffffu, v, off);
                int   oi = __shfl_xor_sync(0xffffffffu, idx, off);
                if (ov > v || (ov == v && oi < idx)) { v = ov; idx = oi; }
            }
            const float mm = v; const int i1 = idx;

            float w0 = (lane == i1) ? NEG_INF : l0;
            float w1 = (lane + 32 == i1) ? NEG_INF : l1;
            float v2; int idx2;
            if (w1 > w0) { v2 = w1; idx2 = lane + 32; } else { v2 = w0; idx2 = lane; }
#pragma unroll
            for (int off = 16; off; off >>= 1) {
                float ov = __shfl_xor_sync(0xffffffffu, v2, off);
                int   oi = __shfl_xor_sync(0xffffffffu, idx2, off);
                if (ov > v2 || (ov == v2 && oi < idx2)) { v2 = ov; idx2 = oi; }
            }

            float s = expf(l0 - mm) + expf(l1 - mm);
#pragma unroll
            for (int off = 16; off; off >>= 1)
                s += __shfl_xor_sync(0xffffffffu, s, off);

            if (lane == 0) {
                const float g1 = 1.0f / s;
                const float g2 = expf(v2 - mm) / s;
                const float denom = g1 + g2;
                const float g2n = g2 / denom;
                const float rnd = jax_uniform_partitionable((uint32_t)i);
                const int w2 = (rnd < 2.0f * g2n) ? 1 : 0;

                const int blkb = i >> 8;
                const int oe1 = g_e1[i], oe2 = g_e2[i], ow2 = g_want2[i];
                if (i1 != oe1) {
                    atomicSub(&g_bc1T[oe1 * 64 + blkb], 1);
                    atomicAdd(&g_bc1T[i1 * 64 + blkb], 1);
                }
                if (ow2) atomicSub(&g_bc2T[oe2 * 64 + blkb], 1);
                if (w2)  atomicAdd(&g_bc2T[idx2 * 64 + blkb], 1);

                g_e1[i] = i1;
                g_e2[i] = idx2;
                g_g1n[i] = g1 / denom;
                g_g2n[i] = g2n;
                g_want2[i] = w2;
            }
        }
        __syncthreads();
    }
}

// ---------------- cross-block scan (transposed, int4) ----------------
__global__ void scan_kernel() {
    const int e = threadIdx.x;
    if (e >= 64) return;
    int4 buf[16];
    const int4* s1 = (const int4*)(g_bc1T + e * 64);
#pragma unroll
    for (int q = 0; q < 16; ++q) buf[q] = s1[q];
    int r1 = 0;
#pragma unroll
    for (int q = 0; q < 16; ++q) {
        g_base1T[e * 64 + q * 4 + 0] = r1; r1 += buf[q].x;
        g_base1T[e * 64 + q * 4 + 1] = r1; r1 += buf[q].y;
        g_base1T[e * 64 + q * 4 + 2] = r1; r1 += buf[q].z;
        g_base1T[e * 64 + q * 4 + 3] = r1; r1 += buf[q].w;
    }
    const int4* s2 = (const int4*)(g_bc2T + e * 64);
#pragma unroll
    for (int q = 0; q < 16; ++q) buf[q] = s2[q];
    int r2 = 0;
#pragma unroll
    for (int q = 0; q < 16; ++q) {
        g_base2T[e * 64 + q * 4 + 0] = r2; r2 += buf[q].x;
        g_base2T[e * 64 + q * 4 + 1] = r2; r2 += buf[q].y;
        g_base2T[e * 64 + q * 4 + 2] = r2; r2 += buf[q].z;
        g_base2T[e * 64 + q * 4 + 3] = r2; r2 += buf[q].w;
    }
    g_cap2[e] = CAP - (r1 < CAP ? r1 : CAP);
}

// ---------------- final ranks + full-row write (zeroing fused) ----------------
__global__ __launch_bounds__(256)
void assign_kernel(float* __restrict__ out) {
    __shared__ int wc1[8][64];
    __shared__ int wc2[8][64];
    const int t = threadIdx.x, warp = t >> 5, lane = t & 31;
    const int blk = blockIdx.x;

    ((int*)wc1)[t] = 0; ((int*)wc1)[t + 256] = 0;
    ((int*)wc2)[t] = 0; ((int*)wc2)[t + 256] = 0;
    __syncthreads();

    const int i  = blk * 256 + t;
    const int e1 = g_e1[i], e2 = g_e2[i], want2 = g_want2[i];
    const unsigned lt = (1u << lane) - 1u;

    const unsigned m1 = __match_any_sync(0xffffffffu, e1);
    const int lr1 = __popc(m1 & lt);
    if (lr1 == 0) wc1[warp][e1] = __popc(m1);

    const unsigned act2 = __ballot_sync(0xffffffffu, want2);
    const unsigned m2 = __match_any_sync(0xffffffffu, e2) & act2;
    const int lr2 = __popc(m2 & lt);
    if (want2 && lr2 == 0) wc2[warp][e2] = __popc(m2);
    __syncthreads();

    int off1 = 0, off2 = 0;
    for (int w = 0; w < warp; ++w) {
        off1 += wc1[w][e1];
        off2 += wc2[w][e2];
    }

    const int pos1 = g_base1T[e1 * 64 + blk] + off1 + lr1 + 1;
    const int pos2 = g_base2T[e2 * 64 + blk] + off2 + lr2 + 1;
    const float val1 = (pos1 <= CAP) ? g_g1n[i] : 0.f;
    const float val2 = (want2 && pos2 <= g_cap2[e2]) ? g_g2n[i] : 0.f;

    float4* op = (float4*)(out + (size_t)i * 64);
#pragma unroll
    for (int q = 0; q < 16; ++q) {
        float4 z = make_float4(0.f, 0.f, 0.f, 0.f);
        if ((e1 >> 2) == q) ((float*)&z)[e1 & 3] = val1;
        if ((e2 >> 2) == q) ((float*)&z)[e2 & 3] = val2;
        op[q] = z;
    }
}

// ---------------- launcher ----------------
extern "C" void kernel_launch(void* const* d_in, const int* in_sizes, int n_in,
                              void* d_out, int out_size) {
    const float* x = (const float*)d_in[0];
    const float* w = (const float*)d_in[1];
    float* out = (float*)d_out;

    cudaFuncSetAttribute(gemm_mma, cudaFuncAttributeMaxDynamicSharedMemorySize, GEMM_SMEM);

    wconv_kernel<<<512, 256>>>(w);
    gemm_mma<<<S_TOK / BM, 512, GEMM_SMEM>>>(x);
    topk256<<<S_TOK / 256, 256>>>();
    rescue_kernel<<<148, 256>>>(x, w);
    scan_kernel<<<1, 64>>>();
    assign_kernel<<<S_TOK / 256, 256>>>(out);
}

// round 8
// speedup vs baseline: 1.6309x; 1.2370x over previous
#include <cuda_runtime.h>
#include <cuda_fp16.h>
#include <cstdint>

#define S_TOK 16384
#define D_DIM 4096
#define N_EXP 64
#define CAP   320
#define KC    64
#define NCHUNK 64
#define BM    128

#define SWZ(o) ((o) ^ (((o) >> 3) & 0x70))

// ---------------- scratch ----------------
__device__ float g_logits[S_TOK * N_EXP];
// W fp16 plane: [chunk][expert][36 words]; rows padded 128B->144B (bank spread)
__device__ __align__(16) uint32_t g_whT[NCHUNK * 2304];
__device__ int   g_e1[S_TOK];
__device__ int   g_e2[S_TOK];
__device__ int   g_want2[S_TOK];
__device__ float g_g1n[S_TOK];
__device__ float g_g2n[S_TOK];
__device__ int   g_bc1T[64 * 64];    // [expert][block]
__device__ int   g_bc2T[64 * 64];
__device__ int   g_base1T[64 * 64];
__device__ int   g_base2T[64 * 64];
__device__ int   g_cap2[64];
__device__ int   g_nflag;
__device__ int   g_flagged[S_TOK];

// ---------------- PTX helpers ----------------
__device__ __forceinline__ uint32_t smem_to_u32(const void* p) {
    uint32_t a;
    asm("{ .reg .u64 t; cvta.to.shared.u64 t, %1; cvt.u32.u64 %0, t; }" : "=r"(a) : "l"(p));
    return a;
}
#define CP_ASYNC16(dst, src) \
    asm volatile("cp.async.cg.shared.global [%0], [%1], 16;" :: "r"(dst), "l"(src) : "memory")
#define CP_ASYNC_COMMIT()  asm volatile("cp.async.commit_group;" ::: "memory")
#define CP_ASYNC_WAIT0()   asm volatile("cp.async.wait_group 0;" ::: "memory")

#define LDSM_X4(r0, r1, r2, r3, addr) \
    asm volatile("ldmatrix.sync.aligned.m8n8.x4.shared.b16 {%0,%1,%2,%3}, [%4];" \
        : "=r"(r0), "=r"(r1), "=r"(r2), "=r"(r3) : "r"(addr))

#define LDS32(r, addr) \
    asm volatile("ld.shared.b32 %0, [%1];" : "=r"(r) : "r"(addr))

#define MMA_FP16(d, a, b0, b1) \
    asm volatile("mma.sync.aligned.m16n8k16.row.col.f32.f16.f16.f32 " \
        "{%0,%1,%2,%3}, {%4,%5,%6,%7}, {%8,%9}, {%0,%1,%2,%3};" \
        : "+f"((d)[0]), "+f"((d)[1]), "+f"((d)[2]), "+f"((d)[3]) \
        : "r"((a)[0]), "r"((a)[1]), "r"((a)[2]), "r"((a)[3]), "r"(b0), "r"(b1))

// gemm smem layout
#define XS(s)  (sb + (s) * 16384)
#define WHS(s) (sb + 32768 + (s) * 9216)
#define GEMM_SMEM 51200

// rescue smem: 4 token rows + 4x64 logits
#define RESCUE_SMEM ((4 * D_DIM + 256) * 4)

// ---------------- W pre-conversion (also resets flag counter) ----------------
__global__ __launch_bounds__(256)
void wconv_kernel(const float* __restrict__ W) {
    const int pid = blockIdx.x * 256 + threadIdx.x;   // 0..131071
    if (pid == 0) g_nflag = 0;
    const int n = pid >> 11;                          // expert 0..63
    const int j = pid & 2047;                         // k-pair 0..2047
    const float2 v = *(const float2*)(W + (size_t)n * D_DIM + j * 2);
    const __half h0 = __float2half_rn(v.x);
    const __half h1 = __float2half_rn(v.y);
    const uint32_t hp = (uint32_t)__half_as_ushort(h0) | ((uint32_t)__half_as_ushort(h1) << 16);
    g_whT[(j >> 5) * 2304 + n * 36 + (j & 31)] = hp;
}

// ---------------- HMMA GEMM: single fp16 product ----------------
__global__ __launch_bounds__(512, 1)
void gemm_mma(const float* __restrict__ X) {
    extern __shared__ __align__(1024) char smem[];
    const uint32_t sb = smem_to_u32(smem);
    const int tid = threadIdx.x, wid = tid >> 5, lane = tid & 31;
    const int m0 = blockIdx.x * BM;
    const int warp_m = wid & 3, warp_n = wid >> 2;   // 4M x 4N, warp tile m32 x n16

    float acc[2][2][4];
#pragma unroll
    for (int a = 0; a < 2; ++a)
#pragma unroll
        for (int b = 0; b < 2; ++b)
#pragma unroll
            for (int q = 0; q < 4; ++q) acc[a][b][q] = 0.f;

    const int xrow = tid >> 2, xc4 = tid & 3;
    const float4* xp = (const float4*)(X + (size_t)(m0 + xrow) * D_DIM);

    const uint32_t a_b0  = (uint32_t)((warp_m * 32 + (lane & 15)) * 128 + (lane >> 4) * 16);
    const uint32_t b_off = (uint32_t)((warp_n * 16 + (lane >> 2)) * 144 + (lane & 3) * 4);

    auto loadB = [&](int c, int s) {
        const char* gh = (const char*)(g_whT + c * 2304);
        const uint32_t wh = WHS(s);
        CP_ASYNC16(wh + tid * 16, gh + tid * 16);
        if (tid < 64) CP_ASYNC16(wh + (512 + tid) * 16, gh + (512 + tid) * 16);
    };
    auto loadx = [&](int c, float4* v) {
#pragma unroll
        for (int it = 0; it < 4; ++it)
            v[it] = xp[c * 16 + xc4 + it * 4];
    };
    auto storeXS = [&](int s, const float4* v) {
        const uint32_t xs = XS(s);
#pragma unroll
        for (int it = 0; it < 4; ++it) {
            const __half2 h01 = __floats2half2_rn(v[it].x, v[it].y);
            const __half2 h23 = __floats2half2_rn(v[it].z, v[it].w);
            const uint32_t p0 = *(const uint32_t*)&h01;
            const uint32_t p1 = *(const uint32_t*)&h23;
            const uint32_t off = SWZ((uint32_t)(xrow * 128 + (xc4 + it * 4) * 8));
            asm volatile("st.shared.v2.b32 [%0], {%1,%2};" :: "r"(xs + off), "r"(p0), "r"(p1) : "memory");
        }
    };

    // prologue
    float4 v[4];
    loadB(0, 0);
    CP_ASYNC_COMMIT();
    loadx(0, v);
    storeXS(0, v);
    CP_ASYNC_WAIT0();
    __syncthreads();

    for (int c = 0; c < NCHUNK; ++c) {
        const int s = c & 1;
        float4 nv[4];
        if (c + 1 < NCHUNK) {
            loadB(c + 1, s ^ 1);
            CP_ASYNC_COMMIT();
            loadx(c + 1, nv);
        }
        const uint32_t xs = XS(s), wh = WHS(s);
#pragma unroll
        for (int ks = 0; ks < 4; ++ks) {
            uint32_t ah[2][4];
            LDSM_X4(ah[0][0], ah[0][1], ah[0][2], ah[0][3], xs + SWZ(a_b0 + ks * 32));
            LDSM_X4(ah[1][0], ah[1][1], ah[1][2], ah[1][3], xs + SWZ(a_b0 + 2048 + ks * 32));
            uint32_t bh[2][2];
#pragma unroll
            for (int nt = 0; nt < 2; ++nt) {
                const uint32_t bo = b_off + nt * 1152 + ks * 32;
                LDS32(bh[nt][0], wh + bo);
                LDS32(bh[nt][1], wh + bo + 16);
            }
#pragma unroll
            for (int mt = 0; mt < 2; ++mt)
#pragma unroll
                for (int nt = 0; nt < 2; ++nt)
                    MMA_FP16(acc[mt][nt], ah[mt], bh[nt][0], bh[nt][1]);
        }
        if (c + 1 < NCHUNK) storeXS(s ^ 1, nv);
        CP_ASYNC_WAIT0();
        __syncthreads();
    }

    const int r0 = m0 + warp_m * 32 + (lane >> 2);
    const int c0 = warp_n * 16 + (lane & 3) * 2;
#pragma unroll
    for (int mt = 0; mt < 2; ++mt)
#pragma unroll
        for (int nt = 0; nt < 2; ++nt) {
            const int r = r0 + mt * 16, cc = c0 + nt * 8;
            *(float2*)&g_logits[(size_t)r * 64 + cc]       = make_float2(acc[mt][nt][0], acc[mt][nt][1]);
            *(float2*)&g_logits[(size_t)(r + 8) * 64 + cc] = make_float2(acc[mt][nt][2], acc[mt][nt][3]);
        }
}

// ---------------- Threefry-2x32 (JAX partitionable, key(1)) ----------------
__device__ __forceinline__ void threefry2x32(uint32_t x0, uint32_t x1,
                                             uint32_t& o0, uint32_t& o1) {
    const uint32_t k0 = 0u, k1 = 1u, k2 = 0x1BD11BDBu;
    x0 += k0; x1 += k1;
#define TFR(r) { x0 += x1; x1 = (x1 << (r)) | (x1 >> (32 - (r))); x1 ^= x0; }
    TFR(13) TFR(15) TFR(26) TFR(6)  x0 += k1; x1 += k2 + 1u;
    TFR(17) TFR(29) TFR(16) TFR(24) x0 += k2; x1 += k0 + 2u;
    TFR(13) TFR(15) TFR(26) TFR(6)  x0 += k0; x1 += k1 + 3u;
    TFR(17) TFR(29) TFR(16) TFR(24) x0 += k1; x1 += k2 + 4u;
    TFR(13) TFR(15) TFR(26) TFR(6)  x0 += k2; x1 += k0 + 5u;
#undef TFR
    o0 = x0; o1 = x1;
}
__device__ __forceinline__ float jax_uniform_partitionable(uint32_t i) {
    uint32_t o0, o1;
    threefry2x32(0u, i, o0, o1);
    const uint32_t bits = o0 ^ o1;
    return __uint_as_float((bits >> 9) | 0x3f800000u) - 1.0f;
}

// ---------------- fused topk + softmax + want2 + flags + block histogram ----------------
__global__ __launch_bounds__(256)
void topk256() {
    __shared__ int c1[64], c2[64];
    const int t = threadIdx.x, blk = blockIdx.x;
    const int i = blk * 256 + t;
    if (t < 64) { c1[t] = 0; c2[t] = 0; }
    __syncthreads();

    float4 L[16];
    const float4* lp = (const float4*)(g_logits + (size_t)i * 64);
#pragma unroll
    for (int q = 0; q < 16; ++q) L[q] = lp[q];

    float v1 = -3.4e38f, v2 = -3.4e38f, v3 = -3.4e38f;
    int i1 = 0, i2 = 0;
#pragma unroll
    for (int q = 0; q < 16; ++q) {
        const float e[4] = {L[q].x, L[q].y, L[q].z, L[q].w};
#pragma unroll
        for (int r = 0; r < 4; ++r) {
            const float x = e[r]; const int idx = q * 4 + r;
            if (x > v1)      { v3 = v2; v2 = v1; i2 = i1; v1 = x; i1 = idx; }
            else if (x > v2) { v3 = v2; v2 = x; i2 = idx; }
            else if (x > v3) { v3 = x; }
        }
    }
    float s = 0.f;
#pragma unroll
    for (int q = 0; q < 16; ++q)
        s += expf(L[q].x - v1) + expf(L[q].y - v1) + expf(L[q].z - v1) + expf(L[q].w - v1);

    const float g1 = 1.0f / s;
    const float g2 = expf(v2 - v1) / s;
    const float denom = g1 + g2;
    const float g1n = g1 / denom, g2n = g2 / denom;
    const float rnd = jax_uniform_partitionable((uint32_t)i);
    const int want2 = (rnd < 2.0f * g2n) ? 1 : 0;

    g_e1[i] = i1; g_e2[i] = i2;
    g_g1n[i] = g1n; g_g2n[i] = g2n;
    g_want2[i] = want2;

    const float TAU_GAP = 2e-3f, TAU_RND = 1.2e-3f;
    if ((v1 - v2) < TAU_GAP || (v2 - v3) < TAU_GAP || fabsf(rnd - 2.0f * g2n) < TAU_RND) {
        const int k = atomicAdd(&g_nflag, 1);
        g_flagged[k] = i;
    }
    atomicAdd(&c1[i1], 1);
    if (want2) atomicAdd(&c2[i2], 1);
    __syncthreads();
    if (t < 64) { g_bc1T[t * 64 + blk] = c1[t]; g_bc2T[t * 64 + blk] = c2[t]; }
}

// ---------------- exact fp32 rescue: 4 tokens per block ----------------
__global__ __launch_bounds__(256)
void rescue_kernel(const float* __restrict__ X, const float* __restrict__ W) {
    extern __shared__ __align__(16) float rsm[];   // [4][4096] x rows + [4][64] logits
    float* xs = rsm;
    float* lg = rsm + 4 * D_DIM;
    const int t = threadIdx.x, warp = t >> 5, lane = t & 31;
    const int nf = g_nflag;
    const int ngroups = (nf + 3) >> 2;

    for (int g = blockIdx.x; g < ngroups; g += gridDim.x) {
        const int gbase = g * 4;
        int toks[4];
#pragma unroll
        for (int q = 0; q < 4; ++q) {
            int fi = gbase + q;
            toks[q] = g_flagged[fi < nf ? fi : nf - 1];
        }

        // stage 4 x rows (coalesced)
#pragma unroll
        for (int q = 0; q < 4; ++q) {
            const float4* xr = (const float4*)(X + (size_t)toks[q] * D_DIM);
            float4* xd = (float4*)(xs + q * D_DIM);
#pragma unroll
            for (int it = 0; it < 4; ++it) xd[t + it * 256] = xr[t + it * 256];
        }
        __syncthreads();

        // 8 passes: warp computes expert e = pass*8 + warp against all 4 tokens
#pragma unroll 1
        for (int pass = 0; pass < 8; ++pass) {
            const int e = pass * 8 + warp;
            const float4* wr = (const float4*)(W + (size_t)e * D_DIM);
            float4 a0 = make_float4(0.f, 0.f, 0.f, 0.f);
            float4 a1 = a0, a2 = a0, a3 = a0;
#pragma unroll 4
            for (int j = 0; j < 32; ++j) {
                const float4 wa = wr[j * 32 + lane];
                const float4 x0 = ((const float4*)(xs))[j * 32 + lane];
                const float4 x1 = ((const float4*)(xs + D_DIM))[j * 32 + lane];
                const float4 x2 = ((const float4*)(xs + 2 * D_DIM))[j * 32 + lane];
                const float4 x3 = ((const float4*)(xs + 3 * D_DIM))[j * 32 + lane];
                a0.x = fmaf(x0.x, wa.x, a0.x); a0.y = fmaf(x0.y, wa.y, a0.y);
                a0.z = fmaf(x0.z, wa.z, a0.z); a0.w = fmaf(x0.w, wa.w, a0.w);
                a1.x = fmaf(x1.x, wa.x, a1.x); a1.y = fmaf(x1.y, wa.y, a1.y);
                a1.z = fmaf(x1.z, wa.z, a1.z); a1.w = fmaf(x1.w, wa.w, a1.w);
                a2.x = fmaf(x2.x, wa.x, a2.x); a2.y = fmaf(x2.y, wa.y, a2.y);
                a2.z = fmaf(x2.z, wa.z, a2.z); a2.w = fmaf(x2.w, wa.w, a2.w);
                a3.x = fmaf(x3.x, wa.x, a3.x); a3.y = fmaf(x3.y, wa.y, a3.y);
                a3.z = fmaf(x3.z, wa.z, a3.z); a3.w = fmaf(x3.w, wa.w, a3.w);
            }
            float t0 = ((a0.x + a0.y) + a0.z) + a0.w;
            float t1 = ((a1.x + a1.y) + a1.z) + a1.w;
            float t2 = ((a2.x + a2.y) + a2.z) + a2.w;
            float t3 = ((a3.x + a3.y) + a3.z) + a3.w;
#pragma unroll
            for (int off = 16; off; off >>= 1) {
                t0 += __shfl_xor_sync(0xffffffffu, t0, off);
                t1 += __shfl_xor_sync(0xffffffffu, t1, off);
                t2 += __shfl_xor_sync(0xffffffffu, t2, off);
                t3 += __shfl_xor_sync(0xffffffffu, t3, off);
            }
            if (lane == 0) {
                lg[0 * 64 + e] = t0;
                lg[1 * 64 + e] = t1;
                lg[2 * 64 + e] = t2;
                lg[3 * 64 + e] = t3;
            }
        }
        __syncthreads();

        // decision: warps 0-3 handle tokens 0-3
        if (warp < 4 && (gbase + warp) < nf) {
            const int i = toks[warp];
            const float* lrow = lg + warp * 64;
            const float l0 = lrow[lane];
            const float l1 = lrow[lane + 32];
            const float NEG_INF = __int_as_float(0xff800000);

            float v; int idx;
            if (l1 > l0) { v = l1; idx = lane + 32; } else { v = l0; idx = lane; }
#pragma unroll
            for (int off = 16; off; off >>= 1) {
                float ov = __shfl_xor_sync(0xffffffffu, v, off);
                int   oi = __shfl_xor_sync(0xffffffffu, idx, off);
                if (ov > v || (ov == v && oi < idx)) { v = ov; idx = oi; }
            }
            const float mm = v; const int i1 = idx;

            float w0 = (lane == i1) ? NEG_INF : l0;
            float w1 = (lane + 32 == i1) ? NEG_INF : l1;
            float v2; int idx2;
            if (w1 > w0) { v2 = w1; idx2 = lane + 32; } else { v2 = w0; idx2 = lane; }
#pragma unroll
            for (int off = 16; off; off >>= 1) {
                float ov = __shfl_xor_sync(0xffffffffu, v2, off);
                int   oi = __shfl_xor_sync(0xffffffffu, idx2, off);
                if (ov > v2 || (ov == v2 && oi < idx2)) { v2 = ov; idx2 = oi; }
            }

            float s = expf(l0 - mm) + expf(l1 - mm);
#pragma unroll
            for (int off = 16; off; off >>= 1)
                s += __shfl_xor_sync(0xffffffffu, s, off);

            if (lane == 0) {
                const float g1 = 1.0f / s;
                const float g2 = expf(v2 - mm) / s;
                const float denom = g1 + g2;
                const float g2n = g2 / denom;
                const float rnd = jax_uniform_partitionable((uint32_t)i);
                const int w2 = (rnd < 2.0f * g2n) ? 1 : 0;

                const int blkb = i >> 8;
                const int oe1 = g_e1[i], oe2 = g_e2[i], ow2 = g_want2[i];
                if (i1 != oe1) {
                    atomicSub(&g_bc1T[oe1 * 64 + blkb], 1);
                    atomicAdd(&g_bc1T[i1 * 64 + blkb], 1);
                }
                if (ow2) atomicSub(&g_bc2T[oe2 * 64 + blkb], 1);
                if (w2)  atomicAdd(&g_bc2T[idx2 * 64 + blkb], 1);

                g_e1[i] = i1;
                g_e2[i] = idx2;
                g_g1n[i] = g1 / denom;
                g_g2n[i] = g2n;
                g_want2[i] = w2;
            }
        }
        __syncthreads();
    }
}

// ---------------- cross-block scan (transposed, int4) ----------------
__global__ void scan_kernel() {
    const int e = threadIdx.x;
    if (e >= 64) return;
    int4 buf[16];
    const int4* s1 = (const int4*)(g_bc1T + e * 64);
#pragma unroll
    for (int q = 0; q < 16; ++q) buf[q] = s1[q];
    int r1 = 0;
#pragma unroll
    for (int q = 0; q < 16; ++q) {
        g_base1T[e * 64 + q * 4 + 0] = r1; r1 += buf[q].x;
        g_base1T[e * 64 + q * 4 + 1] = r1; r1 += buf[q].y;
        g_base1T[e * 64 + q * 4 + 2] = r1; r1 += buf[q].z;
        g_base1T[e * 64 + q * 4 + 3] = r1; r1 += buf[q].w;
    }
    const int4* s2 = (const int4*)(g_bc2T + e * 64);
#pragma unroll
    for (int q = 0; q < 16; ++q) buf[q] = s2[q];
    int r2 = 0;
#pragma unroll
    for (int q = 0; q < 16; ++q) {
        g_base2T[e * 64 + q * 4 + 0] = r2; r2 += buf[q].x;
        g_base2T[e * 64 + q * 4 + 1] = r2; r2 += buf[q].y;
        g_base2T[e * 64 + q * 4 + 2] = r2; r2 += buf[q].z;
        g_base2T[e * 64 + q * 4 + 3] = r2; r2 += buf[q].w;
    }
    g_cap2[e] = CAP - (r1 < CAP ? r1 : CAP);
}

// ---------------- final ranks + full-row write (zeroing fused) ----------------
__global__ __launch_bounds__(256)
void assign_kernel(float* __restrict__ out) {
    __shared__ int wc1[8][64];
    __shared__ int wc2[8][64];
    const int t = threadIdx.x, warp = t >> 5, lane = t & 31;
    const int blk = blockIdx.x;

    ((int*)wc1)[t] = 0; ((int*)wc1)[t + 256] = 0;
    ((int*)wc2)[t] = 0; ((int*)wc2)[t + 256] = 0;
    __syncthreads();

    const int i  = blk * 256 + t;
    const int e1 = g_e1[i], e2 = g_e2[i], want2 = g_want2[i];
    const unsigned lt = (1u << lane) - 1u;

    const unsigned m1 = __match_any_sync(0xffffffffu, e1);
    const int lr1 = __popc(m1 & lt);
    if (lr1 == 0) wc1[warp][e1] = __popc(m1);

    const unsigned act2 = __ballot_sync(0xffffffffu, want2);
    const unsigned m2 = __match_any_sync(0xffffffffu, e2) & act2;
    const int lr2 = __popc(m2 & lt);
    if (want2 && lr2 == 0) wc2[warp][e2] = __popc(m2);
    __syncthreads();

    int off1 = 0, off2 = 0;
    for (int w = 0; w < warp; ++w) {
        off1 += wc1[w][e1];
        off2 += wc2[w][e2];
    }

    const int pos1 = g_base1T[e1 * 64 + blk] + off1 + lr1 + 1;
    const int pos2 = g_base2T[e2 * 64 + blk] + off2 + lr2 + 1;
    const float val1 = (pos1 <= CAP) ? g_g1n[i] : 0.f;
    const float val2 = (want2 && pos2 <= g_cap2[e2]) ? g_g2n[i] : 0.f;

    float4* op = (float4*)(out + (size_t)i * 64);
#pragma unroll
    for (int q = 0; q < 16; ++q) {
        float4 z = make_float4(0.f, 0.f, 0.f, 0.f);
        if ((e1 >> 2) == q) ((float*)&z)[e1 & 3] = val1;
        if ((e2 >> 2) == q) ((float*)&z)[e2 & 3] = val2;
        op[q] = z;
    }
}

// ---------------- launcher ----------------
extern "C" void kernel_launch(void* const* d_in, const int* in_sizes, int n_in,
                              void* d_out, int out_size) {
    const float* x = (const float*)d_in[0];
    const float* w = (const float*)d_in[1];
    float* out = (float*)d_out;

    cudaFuncSetAttribute(gemm_mma, cudaFuncAttributeMaxDynamicSharedMemorySize, GEMM_SMEM);
    cudaFuncSetAttribute(rescue_kernel, cudaFuncAttributeMaxDynamicSharedMemorySize, RESCUE_SMEM);

    wconv_kernel<<<512, 256>>>(w);
    gemm_mma<<<S_TOK / BM, 512, GEMM_SMEM>>>(x);
    topk256<<<S_TOK / 256, 256>>>();
    rescue_kernel<<<148, 256, RESCUE_SMEM>>>(x, w);
    scan_kernel<<<1, 64>>>();
    assign_kernel<<<S_TOK / 256, 256>>>(out);
}

// round 9
// speedup vs baseline: 1.6906x; 1.0366x over previous
#include <cuda_runtime.h>
#include <cuda_fp16.h>
#include <cstdint>

#define S_TOK 16384
#define D_DIM 4096
#define N_EXP 64
#define CAP   320
#define KC    64
#define NCHUNK 64
#define BM    128

#define SWZ(o) ((o) ^ (((o) >> 3) & 0x70))

// ---------------- scratch ----------------
__device__ float g_logits[S_TOK * N_EXP];
// W fp16 plane: [chunk][expert][36 words]; rows padded 128B->144B (bank spread)
__device__ __align__(16) uint32_t g_whT[NCHUNK * 2304];
__device__ int   g_e1[S_TOK];
__device__ int   g_e2[S_TOK];
__device__ int   g_want2[S_TOK];
__device__ float g_g1n[S_TOK];
__device__ float g_g2n[S_TOK];
__device__ int   g_bc1T[64 * 64];    // [expert][block]
__device__ int   g_bc2T[64 * 64];
__device__ int   g_base1T[64 * 64];
__device__ int   g_base2T[64 * 64];
__device__ int   g_cap2[64];
__device__ int   g_nflag;
__device__ int   g_flagged[S_TOK];

// ---------------- PTX helpers ----------------
__device__ __forceinline__ uint32_t smem_to_u32(const void* p) {
    uint32_t a;
    asm("{ .reg .u64 t; cvta.to.shared.u64 t, %1; cvt.u32.u64 %0, t; }" : "=r"(a) : "l"(p));
    return a;
}
#define CP_ASYNC16(dst, src) \
    asm volatile("cp.async.cg.shared.global [%0], [%1], 16;" :: "r"(dst), "l"(src) : "memory")
#define CP_ASYNC_COMMIT()  asm volatile("cp.async.commit_group;" ::: "memory")
#define CP_ASYNC_WAIT0()   asm volatile("cp.async.wait_group 0;" ::: "memory")

#define LDSM_X4(r0, r1, r2, r3, addr) \
    asm volatile("ldmatrix.sync.aligned.m8n8.x4.shared.b16 {%0,%1,%2,%3}, [%4];" \
        : "=r"(r0), "=r"(r1), "=r"(r2), "=r"(r3) : "r"(addr))

#define LDS32(r, addr) \
    asm volatile("ld.shared.b32 %0, [%1];" : "=r"(r) : "r"(addr))

#define MMA_FP16(d, a, b0, b1) \
    asm volatile("mma.sync.aligned.m16n8k16.row.col.f32.f16.f16.f32 " \
        "{%0,%1,%2,%3}, {%4,%5,%6,%7}, {%8,%9}, {%0,%1,%2,%3};" \
        : "+f"((d)[0]), "+f"((d)[1]), "+f"((d)[2]), "+f"((d)[3]) \
        : "r"((a)[0]), "r"((a)[1]), "r"((a)[2]), "r"((a)[3]), "r"(b0), "r"(b1))

// gemm smem layout
#define XS(s)  (sb + (s) * 16384)
#define WHS(s) (sb + 32768 + (s) * 9216)
#define GEMM_SMEM 51200

// ---------------- W pre-conversion (also resets flag counter) ----------------
__global__ __launch_bounds__(256)
void wconv_kernel(const float* __restrict__ W) {
    const int pid = blockIdx.x * 256 + threadIdx.x;   // 0..131071
    if (pid == 0) g_nflag = 0;
    const int n = pid >> 11;                          // expert 0..63
    const int j = pid & 2047;                         // k-pair 0..2047
    const float2 v = *(const float2*)(W + (size_t)n * D_DIM + j * 2);
    const __half h0 = __float2half_rn(v.x);
    const __half h1 = __float2half_rn(v.y);
    const uint32_t hp = (uint32_t)__half_as_ushort(h0) | ((uint32_t)__half_as_ushort(h1) << 16);
    g_whT[(j >> 5) * 2304 + n * 36 + (j & 31)] = hp;
}

// ---------------- HMMA GEMM: single fp16 product ----------------
__global__ __launch_bounds__(512, 1)
void gemm_mma(const float* __restrict__ X) {
    extern __shared__ __align__(1024) char smem[];
    const uint32_t sb = smem_to_u32(smem);
    const int tid = threadIdx.x, wid = tid >> 5, lane = tid & 31;
    const int m0 = blockIdx.x * BM;
    const int warp_m = wid & 3, warp_n = wid >> 2;   // 4M x 4N, warp tile m32 x n16

    float acc[2][2][4];
#pragma unroll
    for (int a = 0; a < 2; ++a)
#pragma unroll
        for (int b = 0; b < 2; ++b)
#pragma unroll
            for (int q = 0; q < 4; ++q) acc[a][b][q] = 0.f;

    const int xrow = tid >> 2, xc4 = tid & 3;
    const float4* xp = (const float4*)(X + (size_t)(m0 + xrow) * D_DIM);

    const uint32_t a_b0  = (uint32_t)((warp_m * 32 + (lane & 15)) * 128 + (lane >> 4) * 16);
    const uint32_t b_off = (uint32_t)((warp_n * 16 + (lane >> 2)) * 144 + (lane & 3) * 4);

    auto loadB = [&](int c, int s) {
        const char* gh = (const char*)(g_whT + c * 2304);
        const uint32_t wh = WHS(s);
        CP_ASYNC16(wh + tid * 16, gh + tid * 16);
        if (tid < 64) CP_ASYNC16(wh + (512 + tid) * 16, gh + (512 + tid) * 16);
    };
    auto loadx = [&](int c, float4* v) {
#pragma unroll
        for (int it = 0; it < 4; ++it)
            v[it] = xp[c * 16 + xc4 + it * 4];
    };
    auto storeXS = [&](int s, const float4* v) {
        const uint32_t xs = XS(s);
#pragma unroll
        for (int it = 0; it < 4; ++it) {
            const __half2 h01 = __floats2half2_rn(v[it].x, v[it].y);
            const __half2 h23 = __floats2half2_rn(v[it].z, v[it].w);
            const uint32_t p0 = *(const uint32_t*)&h01;
            const uint32_t p1 = *(const uint32_t*)&h23;
            const uint32_t off = SWZ((uint32_t)(xrow * 128 + (xc4 + it * 4) * 8));
            asm volatile("st.shared.v2.b32 [%0], {%1,%2};" :: "r"(xs + off), "r"(p0), "r"(p1) : "memory");
        }
    };

    // prologue
    float4 v[4];
    loadB(0, 0);
    CP_ASYNC_COMMIT();
    loadx(0, v);
    storeXS(0, v);
    CP_ASYNC_WAIT0();
    __syncthreads();

    for (int c = 0; c < NCHUNK; ++c) {
        const int s = c & 1;
        float4 nv[4];
        if (c + 1 < NCHUNK) {
            loadB(c + 1, s ^ 1);
            CP_ASYNC_COMMIT();
            loadx(c + 1, nv);
        }
        const uint32_t xs = XS(s), wh = WHS(s);
#pragma unroll
        for (int ks = 0; ks < 4; ++ks) {
            uint32_t ah[2][4];
            LDSM_X4(ah[0][0], ah[0][1], ah[0][2], ah[0][3], xs + SWZ(a_b0 + ks * 32));
            LDSM_X4(ah[1][0], ah[1][1], ah[1][2], ah[1][3], xs + SWZ(a_b0 + 2048 + ks * 32));
            uint32_t bh[2][2];
#pragma unroll
            for (int nt = 0; nt < 2; ++nt) {
                const uint32_t bo = b_off + nt * 1152 + ks * 32;
                LDS32(bh[nt][0], wh + bo);
                LDS32(bh[nt][1], wh + bo + 16);
            }
#pragma unroll
            for (int mt = 0; mt < 2; ++mt)
#pragma unroll
                for (int nt = 0; nt < 2; ++nt)
                    MMA_FP16(acc[mt][nt], ah[mt], bh[nt][0], bh[nt][1]);
        }
        if (c + 1 < NCHUNK) storeXS(s ^ 1, nv);
        CP_ASYNC_WAIT0();
        __syncthreads();
    }

    const int r0 = m0 + warp_m * 32 + (lane >> 2);
    const int c0 = warp_n * 16 + (lane & 3) * 2;
#pragma unroll
    for (int mt = 0; mt < 2; ++mt)
#pragma unroll
        for (int nt = 0; nt < 2; ++nt) {
            const int r = r0 + mt * 16, cc = c0 + nt * 8;
            *(float2*)&g_logits[(size_t)r * 64 + cc]       = make_float2(acc[mt][nt][0], acc[mt][nt][1]);
            *(float2*)&g_logits[(size_t)(r + 8) * 64 + cc] = make_float2(acc[mt][nt][2], acc[mt][nt][3]);
        }
}

// ---------------- Threefry-2x32 (JAX partitionable, key(1)) ----------------
__device__ __forceinline__ void threefry2x32(uint32_t x0, uint32_t x1,
                                             uint32_t& o0, uint32_t& o1) {
    const uint32_t k0 = 0u, k1 = 1u, k2 = 0x1BD11BDBu;
    x0 += k0; x1 += k1;
#define TFR(r) { x0 += x1; x1 = (x1 << (r)) | (x1 >> (32 - (r))); x1 ^= x0; }
    TFR(13) TFR(15) TFR(26) TFR(6)  x0 += k1; x1 += k2 + 1u;
    TFR(17) TFR(29) TFR(16) TFR(24) x0 += k2; x1 += k0 + 2u;
    TFR(13) TFR(15) TFR(26) TFR(6)  x0 += k0; x1 += k1 + 3u;
    TFR(17) TFR(29) TFR(16) TFR(24) x0 += k1; x1 += k2 + 4u;
    TFR(13) TFR(15) TFR(26) TFR(6)  x0 += k2; x1 += k0 + 5u;
#undef TFR
    o0 = x0; o1 = x1;
}
__device__ __forceinline__ float jax_uniform_partitionable(uint32_t i) {
    uint32_t o0, o1;
    threefry2x32(0u, i, o0, o1);
    const uint32_t bits = o0 ^ o1;
    return __uint_as_float((bits >> 9) | 0x3f800000u) - 1.0f;
}

// ---------------- fused topk + softmax + want2 + flags + block histogram ----------------
__global__ __launch_bounds__(256)
void topk256() {
    __shared__ int c1[64], c2[64];
    const int t = threadIdx.x, blk = blockIdx.x;
    const int i = blk * 256 + t;
    if (t < 64) { c1[t] = 0; c2[t] = 0; }
    __syncthreads();

    float4 L[16];
    const float4* lp = (const float4*)(g_logits + (size_t)i * 64);
#pragma unroll
    for (int q = 0; q < 16; ++q) L[q] = lp[q];

    float v1 = -3.4e38f, v2 = -3.4e38f, v3 = -3.4e38f;
    int i1 = 0, i2 = 0;
#pragma unroll
    for (int q = 0; q < 16; ++q) {
        const float e[4] = {L[q].x, L[q].y, L[q].z, L[q].w};
#pragma unroll
        for (int r = 0; r < 4; ++r) {
            const float x = e[r]; const int idx = q * 4 + r;
            if (x > v1)      { v3 = v2; v2 = v1; i2 = i1; v1 = x; i1 = idx; }
            else if (x > v2) { v3 = v2; v2 = x; i2 = idx; }
            else if (x > v3) { v3 = x; }
        }
    }
    float s = 0.f;
#pragma unroll
    for (int q = 0; q < 16; ++q)
        s += expf(L[q].x - v1) + expf(L[q].y - v1) + expf(L[q].z - v1) + expf(L[q].w - v1);

    const float g1 = 1.0f / s;
    const float g2 = expf(v2 - v1) / s;
    const float denom = g1 + g2;
    const float g1n = g1 / denom, g2n = g2 / denom;
    const float rnd = jax_uniform_partitionable((uint32_t)i);
    const int want2 = (rnd < 2.0f * g2n) ? 1 : 0;

    g_e1[i] = i1; g_e2[i] = i2;
    g_g1n[i] = g1n; g_g2n[i] = g2n;
    g_want2[i] = want2;

    const float TAU_GAP = 2e-3f, TAU_RND = 1.2e-3f;
    if ((v1 - v2) < TAU_GAP || (v2 - v3) < TAU_GAP || fabsf(rnd - 2.0f * g2n) < TAU_RND) {
        const int k = atomicAdd(&g_nflag, 1);
        g_flagged[k] = i;
    }
    atomicAdd(&c1[i1], 1);
    if (want2) atomicAdd(&c2[i2], 1);
    __syncthreads();
    if (t < 64) { g_bc1T[t * 64 + blk] = c1[t]; g_bc2T[t * 64 + blk] = c2[t]; }
}

// ---------------- rescue stage 1: exact fp32 logits for flagged tokens ----------------
// grid 512: block = (expert group eg = b&7 [8 experts], token stripe ts = b>>3 [of 64])
// warp w computes expert eg*8+w; writes exact logits back into g_logits rows.
__global__ __launch_bounds__(256)
void rescue_logits(const float* __restrict__ X, const float* __restrict__ W) {
    const int b = blockIdx.x;
    const int eg = b & 7, ts = b >> 3;
    const int warp = threadIdx.x >> 5, lane = threadIdx.x & 31;
    const int e = eg * 8 + warp;
    const int nf = g_nflag;
    const float4* wr = (const float4*)(W + (size_t)e * D_DIM);

    for (int fi = ts; fi < nf; fi += 64) {
        const int i = g_flagged[fi];
        const float4* xr = (const float4*)(X + (size_t)i * D_DIM);
        float a0 = 0.f, a1 = 0.f, a2 = 0.f, a3 = 0.f;
#pragma unroll
        for (int j = 0; j < 32; ++j) {
            const float4 xa = xr[j * 32 + lane];
            const float4 wa = wr[j * 32 + lane];
            a0 = fmaf(xa.x, wa.x, a0);
            a1 = fmaf(xa.y, wa.y, a1);
            a2 = fmaf(xa.z, wa.z, a2);
            a3 = fmaf(xa.w, wa.w, a3);
        }
        float tot = ((a0 + a1) + a2) + a3;
#pragma unroll
        for (int off = 16; off; off >>= 1)
            tot += __shfl_xor_sync(0xffffffffu, tot, off);
        if (lane == 0) g_logits[(size_t)i * 64 + e] = tot;
    }
}

// ---------------- rescue stage 2: decisions + histogram patch (warp per token) ----------------
__global__ __launch_bounds__(256)
void rescue_decide() {
    const int warp = threadIdx.x >> 5, lane = threadIdx.x & 31;
    const int nf = g_nflag;

    for (int fi = blockIdx.x * 8 + warp; fi < nf; fi += gridDim.x * 8) {
        const int i = g_flagged[fi];
        const float l0 = g_logits[(size_t)i * 64 + lane];
        const float l1 = g_logits[(size_t)i * 64 + 32 + lane];
        const float NEG_INF = __int_as_float(0xff800000);

        float v; int idx;
        if (l1 > l0) { v = l1; idx = lane + 32; } else { v = l0; idx = lane; }
#pragma unroll
        for (int off = 16; off; off >>= 1) {
            float ov = __shfl_xor_sync(0xffffffffu, v, off);
            int   oi = __shfl_xor_sync(0xffffffffu, idx, off);
            if (ov > v || (ov == v && oi < idx)) { v = ov; idx = oi; }
        }
        const float mm = v; const int i1 = idx;

        float w0 = (lane == i1) ? NEG_INF : l0;
        float w1 = (lane + 32 == i1) ? NEG_INF : l1;
        float v2; int idx2;
        if (w1 > w0) { v2 = w1; idx2 = lane + 32; } else { v2 = w0; idx2 = lane; }
#pragma unroll
        for (int off = 16; off; off >>= 1) {
            float ov = __shfl_xor_sync(0xffffffffu, v2, off);
            int   oi = __shfl_xor_sync(0xffffffffu, idx2, off);
            if (ov > v2 || (ov == v2 && oi < idx2)) { v2 = ov; idx2 = oi; }
        }

        float s = expf(l0 - mm) + expf(l1 - mm);
#pragma unroll
        for (int off = 16; off; off >>= 1)
            s += __shfl_xor_sync(0xffffffffu, s, off);

        if (lane == 0) {
            const float g1 = 1.0f / s;
            const float g2 = expf(v2 - mm) / s;
            const float denom = g1 + g2;
            const float g2n = g2 / denom;
            const float rnd = jax_uniform_partitionable((uint32_t)i);
            const int w2 = (rnd < 2.0f * g2n) ? 1 : 0;

            const int blkb = i >> 8;
            const int oe1 = g_e1[i], oe2 = g_e2[i], ow2 = g_want2[i];
            if (i1 != oe1) {
                atomicSub(&g_bc1T[oe1 * 64 + blkb], 1);
                atomicAdd(&g_bc1T[i1 * 64 + blkb], 1);
            }
            if (ow2) atomicSub(&g_bc2T[oe2 * 64 + blkb], 1);
            if (w2)  atomicAdd(&g_bc2T[idx2 * 64 + blkb], 1);

            g_e1[i] = i1;
            g_e2[i] = idx2;
            g_g1n[i] = g1 / denom;
            g_g2n[i] = g2n;
            g_want2[i] = w2;
        }
    }
}

// ---------------- cross-block scan (transposed, int4) ----------------
__global__ void scan_kernel() {
    const int e = threadIdx.x;
    if (e >= 64) return;
    int4 buf[16];
    const int4* s1 = (const int4*)(g_bc1T + e * 64);
#pragma unroll
    for (int q = 0; q < 16; ++q) buf[q] = s1[q];
    int r1 = 0;
#pragma unroll
    for (int q = 0; q < 16; ++q) {
        g_base1T[e * 64 + q * 4 + 0] = r1; r1 += buf[q].x;
        g_base1T[e * 64 + q * 4 + 1] = r1; r1 += buf[q].y;
        g_base1T[e * 64 + q * 4 + 2] = r1; r1 += buf[q].z;
        g_base1T[e * 64 + q * 4 + 3] = r1; r1 += buf[q].w;
    }
    const int4* s2 = (const int4*)(g_bc2T + e * 64);
#pragma unroll
    for (int q = 0; q < 16; ++q) buf[q] = s2[q];
    int r2 = 0;
#pragma unroll
    for (int q = 0; q < 16; ++q) {
        g_base2T[e * 64 + q * 4 + 0] = r2; r2 += buf[q].x;
        g_base2T[e * 64 + q * 4 + 1] = r2; r2 += buf[q].y;
        g_base2T[e * 64 + q * 4 + 2] = r2; r2 += buf[q].z;
        g_base2T[e * 64 + q * 4 + 3] = r2; r2 += buf[q].w;
    }
    g_cap2[e] = CAP - (r1 < CAP ? r1 : CAP);
}

// ---------------- final ranks + full-row write (zeroing fused) ----------------
__global__ __launch_bounds__(256)
void assign_kernel(float* __restrict__ out) {
    __shared__ int wc1[8][64];
    __shared__ int wc2[8][64];
    const int t = threadIdx.x, warp = t >> 5, lane = t & 31;
    const int blk = blockIdx.x;

    ((int*)wc1)[t] = 0; ((int*)wc1)[t + 256] = 0;
    ((int*)wc2)[t] = 0; ((int*)wc2)[t + 256] = 0;
    __syncthreads();

    const int i  = blk * 256 + t;
    const int e1 = g_e1[i], e2 = g_e2[i], want2 = g_want2[i];
    const unsigned lt = (1u << lane) - 1u;

    const unsigned m1 = __match_any_sync(0xffffffffu, e1);
    const int lr1 = __popc(m1 & lt);
    if (lr1 == 0) wc1[warp][e1] = __popc(m1);

    const unsigned act2 = __ballot_sync(0xffffffffu, want2);
    const unsigned m2 = __match_any_sync(0xffffffffu, e2) & act2;
    const int lr2 = __popc(m2 & lt);
    if (want2 && lr2 == 0) wc2[warp][e2] = __popc(m2);
    __syncthreads();

    int off1 = 0, off2 = 0;
    for (int w = 0; w < warp; ++w) {
        off1 += wc1[w][e1];
        off2 += wc2[w][e2];
    }

    const int pos1 = g_base1T[e1 * 64 + blk] + off1 + lr1 + 1;
    const int pos2 = g_base2T[e2 * 64 + blk] + off2 + lr2 + 1;
    const float val1 = (pos1 <= CAP) ? g_g1n[i] : 0.f;
    const float val2 = (want2 && pos2 <= g_cap2[e2]) ? g_g2n[i] : 0.f;

    float4* op = (float4*)(out + (size_t)i * 64);
#pragma unroll
    for (int q = 0; q < 16; ++q) {
        float4 z = make_float4(0.f, 0.f, 0.f, 0.f);
        if ((e1 >> 2) == q) ((float*)&z)[e1 & 3] = val1;
        if ((e2 >> 2) == q) ((float*)&z)[e2 & 3] = val2;
        op[q] = z;
    }
}

// ---------------- launcher ----------------
extern "C" void kernel_launch(void* const* d_in, const int* in_sizes, int n_in,
                              void* d_out, int out_size) {
    const float* x = (const float*)d_in[0];
    const float* w = (const float*)d_in[1];
    float* out = (float*)d_out;

    cudaFuncSetAttribute(gemm_mma, cudaFuncAttributeMaxDynamicSharedMemorySize, GEMM_SMEM);

    wconv_kernel<<<512, 256>>>(w);
    gemm_mma<<<S_TOK / BM, 512, GEMM_SMEM>>>(x);
    topk256<<<S_TOK / 256, 256>>>();
    rescue_logits<<<512, 256>>>(x, w);
    rescue_decide<<<148, 256>>>();
    scan_kernel<<<1, 64>>>();
    assign_kernel<<<S_TOK / 256, 256>>>(out);
}